// round 1
// baseline (speedup 1.0000x reference)
#include <cuda_runtime.h>
#include <math.h>

#define T_     256
#define B_     128
#define F_     1024
#define U_     512
#define G4U_   2048
#define CODES_ 1024
#define NCTA2  128

// Scratch (device globals: allocation-free rule)
__device__ float g_xz[T_ * G4U_ * B_];    // [t][n][b]  (n = gate*512+unit), 256 MB
__device__ float g_hseq[T_ * U_ * B_];    // [t][u][b], 64 MB
__device__ unsigned g_count;
__device__ volatile unsigned g_gen;

// ---------------------------------------------------------------------------
// Grid barrier: generation-based, self-resetting count, replay-safe
// ---------------------------------------------------------------------------
__device__ __forceinline__ void grid_barrier() {
    __syncthreads();
    if (threadIdx.x == 0) {
        __threadfence();
        unsigned gen = g_gen;
        if (atomicAdd(&g_count, 1u) == NCTA2 - 1) {
            g_count = 0;
            __threadfence();
            g_gen = gen + 1;
        } else {
            while (g_gen == gen) { }
        }
        __threadfence();
    }
    __syncthreads();
}

__device__ __forceinline__ float sigmoidf_(float x) {
    return 1.0f / (1.0f + __expf(-x));
}

// ---------------------------------------------------------------------------
// Kernel 1: xz[t][n][b] = (x @ W_in)[m][n] + b_lstm[n],  m = t*128+b
// C[32768, 2048] = A[32768,1024] * B[1024,2048]; 64x64 tile, 4x4/thread
// ---------------------------------------------------------------------------
__global__ void __launch_bounds__(256) k1_xz(const float* __restrict__ x,
                                             const float* __restrict__ Win,
                                             const float* __restrict__ bl) {
    __shared__ float shA[16][68];   // [k][m] transposed, padded
    __shared__ float shB[16][64];   // [k][n]

    int tid = threadIdx.x;
    int tx = tid & 15, ty = tid >> 4;
    int m0 = blockIdx.y << 6, n0 = blockIdx.x << 6;

    int la_m = tid >> 2;            // 0..63
    int la_k = (tid & 3) << 2;      // 0,4,8,12
    int lb_k = tid >> 4;            // 0..15
    int lb_n = (tid & 15) << 2;     // 0..60

    const float* ax = x + (size_t)(m0 + la_m) * F_ + la_k;
    const float* bw = Win + (size_t)lb_k * G4U_ + n0 + lb_n;

    float acc[4][4];
#pragma unroll
    for (int i = 0; i < 4; i++)
#pragma unroll
        for (int j = 0; j < 4; j++) acc[i][j] = 0.f;

    for (int k0 = 0; k0 < F_; k0 += 16) {
        float4 a4 = *(const float4*)(ax + k0);
        float4 b4 = *(const float4*)(bw + (size_t)k0 * G4U_);
        __syncthreads();
        shA[la_k + 0][la_m] = a4.x;
        shA[la_k + 1][la_m] = a4.y;
        shA[la_k + 2][la_m] = a4.z;
        shA[la_k + 3][la_m] = a4.w;
        *(float4*)&shB[lb_k][lb_n] = b4;
        __syncthreads();
#pragma unroll
        for (int k = 0; k < 16; ++k) {
            float4 av = *(const float4*)&shA[k][ty << 2];
            float4 bv = *(const float4*)&shB[k][tx << 2];
            float a[4] = {av.x, av.y, av.z, av.w};
            float b[4] = {bv.x, bv.y, bv.z, bv.w};
#pragma unroll
            for (int i = 0; i < 4; i++)
#pragma unroll
                for (int j = 0; j < 4; j++) acc[i][j] += a[i] * b[j];
        }
    }

#pragma unroll
    for (int i = 0; i < 4; i++) {
        int m = m0 + (ty << 2) + i;
        int tt = m >> 7;
        int b  = m & 127;
        float* dst = g_xz + (size_t)tt * G4U_ * B_ + b;
#pragma unroll
        for (int j = 0; j < 4; j++) {
            int n = n0 + (tx << 2) + j;
            dst[(size_t)n * B_] = acc[i][j] + __ldg(bl + n);
        }
    }
}

// ---------------------------------------------------------------------------
// Kernel 2: persistent LSTM recurrence. 128 CTAs, CTA j owns units [4j,4j+4).
// c-state in registers; h read from g_hseq[t-1] (L2), W_rec slice in SMEM.
// ---------------------------------------------------------------------------
__global__ void __launch_bounds__(256) k2_rec(const float* __restrict__ Wrec) {
    __shared__ float shw[512][16];  // [k][gate*4 + v]  v=unit-within-CTA

    int tid = threadIdx.x;
    int j = blockIdx.x;

    // Stage W_rec[k][gate*512 + 4j + v] once
#pragma unroll
    for (int it = 0; it < 8; ++it) {
        int idx = (it << 8) + tid;          // 0..2047 float4 slots
        int k = idx >> 2, g = idx & 3;
        float4 w4 = *(const float4*)(Wrec + (size_t)k * G4U_ + (g << 9) + (j << 2));
        *(float4*)&shw[k][g << 2] = w4;
    }
    __syncthreads();

    int r  = tid & 127;                     // batch row
    int uu = tid >> 7;                      // 0/1: unit pair within CTA
    int u0 = (j << 2) + (uu << 1);          // first of this thread's 2 units

    float c0 = 0.f, c1 = 0.f;

    for (int t = 0; t < T_; ++t) {
        const float* pz = g_xz + ((size_t)t * G4U_ + u0) * B_ + r;
        float acc[4][2];
#pragma unroll
        for (int g = 0; g < 4; ++g) {
            acc[g][0] = pz[(size_t)g * (U_ * B_)];
            acc[g][1] = pz[(size_t)g * (U_ * B_) + B_];
        }

        if (t > 0) {
            grid_barrier();  // h_seq[t-1] writes now globally visible
            const float* hp = g_hseq + (size_t)(t - 1) * U_ * B_ + r;
#pragma unroll 4
            for (int k = 0; k < U_; ++k) {
                float hv = __ldg(hp + (size_t)k * B_);
                const float* wr = &shw[k][uu << 1];
#pragma unroll
                for (int g = 0; g < 4; ++g) {
                    float2 w2 = *(const float2*)(wr + (g << 2));
                    acc[g][0] += hv * w2.x;
                    acc[g][1] += hv * w2.y;
                }
            }
        }

        // Keras gate order: i, f, g, o
        float i0 = sigmoidf_(acc[0][0]), i1 = sigmoidf_(acc[0][1]);
        float f0 = sigmoidf_(acc[1][0]), f1 = sigmoidf_(acc[1][1]);
        float g0 = tanhf(acc[2][0]),     g1 = tanhf(acc[2][1]);
        float o0 = sigmoidf_(acc[3][0]), o1 = sigmoidf_(acc[3][1]);
        c0 = f0 * c0 + i0 * g0;
        c1 = f1 * c1 + i1 * g1;
        float h0 = o0 * tanhf(c0);
        float h1 = o1 * tanhf(c1);

        float* ho = g_hseq + ((size_t)t * U_ + u0) * B_ + r;
        ho[0]  = h0;
        ho[B_] = h1;
    }
}

// ---------------------------------------------------------------------------
// Kernel 3: out = softmax(relu((h*mask) @ W_dense + b_dense))
// CTA = 16 rows (same t, 16 consecutive b) x 1024 cols; thread = 16 rows x 4 cols
// ---------------------------------------------------------------------------
__global__ void __launch_bounds__(256) k3_out(const float* __restrict__ Wd,
                                              const float* __restrict__ bd,
                                              const float* __restrict__ mask,
                                              float* __restrict__ out) {
    __shared__ float shh[512][16];  // [u][row], pre-multiplied by mask
    __shared__ float sred[16][9];

    int tid = threadIdx.x;
    int blk = blockIdx.x;
    int t  = blk >> 3;
    int b0 = (blk & 7) << 4;

#pragma unroll
    for (int it = 0; it < 8; ++it) {
        int idx = (it << 8) + tid;          // 0..2047 float4 slots
        int u = idx >> 2, iq = (idx & 3) << 2;
        float4 h4 = *(const float4*)(g_hseq + ((size_t)t * U_ + u) * B_ + b0 + iq);
        float4 m4 = *(const float4*)(mask + t * B_ + b0 + iq);
        h4.x *= m4.x; h4.y *= m4.y; h4.z *= m4.z; h4.w *= m4.w;
        *(float4*)&shh[u][iq] = h4;
    }
    __syncthreads();

    int c4 = tid << 2;
    float acc[16][4];
#pragma unroll
    for (int rr = 0; rr < 16; rr++)
#pragma unroll
        for (int jj = 0; jj < 4; jj++) acc[rr][jj] = 0.f;

#pragma unroll 2
    for (int u = 0; u < U_; ++u) {
        float4 w4 = *(const float4*)(Wd + (size_t)u * CODES_ + c4);
#pragma unroll
        for (int rq = 0; rq < 4; ++rq) {
            float4 h4 = *(const float4*)&shh[u][rq << 2];
            float hs[4] = {h4.x, h4.y, h4.z, h4.w};
#pragma unroll
            for (int i = 0; i < 4; i++) {
                acc[rq * 4 + i][0] += hs[i] * w4.x;
                acc[rq * 4 + i][1] += hs[i] * w4.y;
                acc[rq * 4 + i][2] += hs[i] * w4.z;
                acc[rq * 4 + i][3] += hs[i] * w4.w;
            }
        }
    }

    // bias + relu, then rowwise softmax across the CTA
    float4 b4 = *(const float4*)(bd + c4);
    float bb[4] = {b4.x, b4.y, b4.z, b4.w};
    int wid = tid >> 5, lane = tid & 31;

    float rmax[16];
#pragma unroll
    for (int rr = 0; rr < 16; ++rr) {
        float m = -1e30f;
#pragma unroll
        for (int i = 0; i < 4; i++) {
            float v = fmaxf(acc[rr][i] + bb[i], 0.f);
            acc[rr][i] = v;
            m = fmaxf(m, v);
        }
#pragma unroll
        for (int s = 16; s > 0; s >>= 1) m = fmaxf(m, __shfl_xor_sync(0xFFFFFFFFu, m, s));
        rmax[rr] = m;
    }
    if (lane == 0) {
#pragma unroll
        for (int rr = 0; rr < 16; ++rr) sred[rr][wid] = rmax[rr];
    }
    __syncthreads();
    if (tid < 16) {
        float m = sred[tid][0];
#pragma unroll
        for (int w = 1; w < 8; w++) m = fmaxf(m, sred[tid][w]);
        sred[tid][8] = m;
    }
    __syncthreads();
#pragma unroll
    for (int rr = 0; rr < 16; ++rr) rmax[rr] = sred[rr][8];

    float rsum[16];
#pragma unroll
    for (int rr = 0; rr < 16; ++rr) {
        float s = 0.f;
#pragma unroll
        for (int i = 0; i < 4; i++) {
            float e = __expf(acc[rr][i] - rmax[rr]);
            acc[rr][i] = e;
            s += e;
        }
#pragma unroll
        for (int st = 16; st > 0; st >>= 1) s += __shfl_xor_sync(0xFFFFFFFFu, s, st);
        rsum[rr] = s;
    }
    if (lane == 0) {
#pragma unroll
        for (int rr = 0; rr < 16; ++rr) sred[rr][wid] = rsum[rr];
    }
    __syncthreads();
    if (tid < 16) {
        float s = 0.f;
#pragma unroll
        for (int w = 0; w < 8; w++) s += sred[tid][w];
        sred[tid][8] = s;
    }
    __syncthreads();

#pragma unroll
    for (int rr = 0; rr < 16; ++rr) {
        float inv = __frcp_rn(sred[rr][8]);
        float4 o;
        o.x = acc[rr][0] * inv;
        o.y = acc[rr][1] * inv;
        o.z = acc[rr][2] * inv;
        o.w = acc[rr][3] * inv;
        *(float4*)(out + (size_t)(t * B_ + b0 + rr) * CODES_ + c4) = o;
    }
}

// ---------------------------------------------------------------------------
extern "C" void kernel_launch(void* const* d_in, const int* in_sizes, int n_in,
                              void* d_out, int out_size) {
    const float* x    = (const float*)d_in[0];
    const float* mask = (const float*)d_in[1];
    const float* Win  = (const float*)d_in[2];
    const float* Wrec = (const float*)d_in[3];
    const float* bl   = (const float*)d_in[4];
    const float* Wd   = (const float*)d_in[5];
    const float* bd   = (const float*)d_in[6];
    float* out = (float*)d_out;

    dim3 g1(G4U_ / 64, (T_ * B_) / 64);
    k1_xz<<<g1, 256>>>(x, Win, bl);
    k2_rec<<<NCTA2, 256>>>(Wrec);
    k3_out<<<(T_ * B_) / 16, 256>>>(Wd, bd, mask, out);
}

// round 5
// speedup vs baseline: 1.1244x; 1.1244x over previous
#include <cuda_runtime.h>
#include <math.h>

#define T_     256
#define B_     128
#define F_     1024
#define U_     512
#define G4U_   2048
#define CODES_ 1024
#define NCTA2  128

typedef unsigned long long u64;

// Scratch (device globals: allocation-free rule)
__device__ float g_xz[(size_t)T_ * G4U_ * B_];   // [t][n][b]  (n = gate*512+unit)
__device__ float g_hseq[(size_t)T_ * U_ * B_];   // [t][u][b]
__device__ unsigned g_count;
__device__ volatile unsigned g_gen;

// ---------------------------------------------------------------------------
// Packed fp32x2 helpers (Blackwell FFMA2)
// ---------------------------------------------------------------------------
__device__ __forceinline__ void ffma2(u64& d, u64 a, u64 b) {
    asm("fma.rn.f32x2 %0, %1, %2, %0;" : "+l"(d) : "l"(a), "l"(b));
}
__device__ __forceinline__ u64 dup2(float x) {
    u64 r;
    asm("mov.b64 %0, {%1, %1};" : "=l"(r) : "f"(x));
    return r;
}
__device__ __forceinline__ u64 pack2(float lo, float hi) {
    u64 r;
    asm("mov.b64 %0, {%1, %2};" : "=l"(r) : "f"(lo), "f"(hi));
    return r;
}
__device__ __forceinline__ float2 unpack2(u64 v) {
    float2 f;
    asm("mov.b64 {%0, %1}, %2;" : "=f"(f.x), "=f"(f.y) : "l"(v));
    return f;
}

__device__ __forceinline__ void grid_barrier() {
    __threadfence();
    __syncthreads();
    if (threadIdx.x == 0) {
        unsigned gen = g_gen;
        if (atomicAdd(&g_count, 1u) == NCTA2 - 1) {
            g_count = 0;
            __threadfence();
            g_gen = gen + 1;
        } else {
            while (g_gen == gen) { __nanosleep(64); }
        }
        __threadfence();
    }
    __syncthreads();
}

__device__ __forceinline__ float sigmoidf_(float x) {
    return __fdividef(1.0f, 1.0f + __expf(-x));
}
// tanh(x) = 1 - 2/(1 + e^{2x});  safe at +-inf via MUFU.RCP(inf)=0
__device__ __forceinline__ float tanhf_fast(float x) {
    float e = __expf(2.0f * x);
    return 1.0f - __fdividef(2.0f, 1.0f + e);
}

// ---------------------------------------------------------------------------
// Kernel 1: xz[t][n][b] = (x @ W_in)[m][n] + b_lstm[n],  m = t*128+b
// 128x128 tile (one full t per CTA), 8n x 8m per thread, f32x2 packed along m.
// ---------------------------------------------------------------------------
__global__ void __launch_bounds__(256) k1_xz(const float* __restrict__ x,
                                             const float* __restrict__ Win,
                                             const float* __restrict__ bl) {
    __shared__ __align__(16) float shA[16 * 132];   // [k][m], padded
    __shared__ __align__(16) float shBd[16 * 256];  // [k][2n] duplicated

    int tid = threadIdx.x;
    int tx = tid & 15;        // m-group
    int ty = tid >> 4;        // n-group
    int t  = blockIdx.y;
    int n0 = blockIdx.x << 7;

    u64 acc[8][4];
#pragma unroll
    for (int i = 0; i < 8; i++)
#pragma unroll
        for (int j = 0; j < 4; j++) acc[i][j] = 0ull;

    int wn = tid & 127;
    int wk = tid >> 7;

    for (int k0 = 0; k0 < F_; k0 += 16) {
        float4 xa[2];
#pragma unroll
        for (int p = 0; p < 2; p++) {
            int idx = (p << 8) + tid;
            int row = idx >> 2, q = idx & 3;
            xa[p] = *(const float4*)(x + (size_t)(t * 128 + row) * F_ + k0 + (q << 2));
        }
        float wv[8];
#pragma unroll
        for (int p = 0; p < 8; p++) {
            int k = (p << 1) + wk;
            wv[p] = Win[(size_t)(k0 + k) * G4U_ + n0 + wn];
        }
        __syncthreads();
#pragma unroll
        for (int p = 0; p < 2; p++) {
            int idx = (p << 8) + tid;
            int row = idx >> 2, q = idx & 3;
            shA[((q << 2) + 0) * 132 + row] = xa[p].x;
            shA[((q << 2) + 1) * 132 + row] = xa[p].y;
            shA[((q << 2) + 2) * 132 + row] = xa[p].z;
            shA[((q << 2) + 3) * 132 + row] = xa[p].w;
        }
#pragma unroll
        for (int p = 0; p < 8; p++) {
            int k = (p << 1) + wk;
            *(u64*)&shBd[k * 256 + wn * 2] = dup2(wv[p]);
        }
        __syncthreads();
#pragma unroll 4
        for (int k = 0; k < 16; ++k) {
            ulonglong2 A0 = *(const ulonglong2*)&shA[k * 132 + (tx << 2)];
            ulonglong2 A1 = *(const ulonglong2*)&shA[k * 132 + (tx << 2) + 64];
            ulonglong2 B0 = *(const ulonglong2*)&shBd[k * 256 + (ty << 3)];
            ulonglong2 B1 = *(const ulonglong2*)&shBd[k * 256 + (ty << 3) + 4];
            ulonglong2 B2 = *(const ulonglong2*)&shBd[k * 256 + 128 + (ty << 3)];
            ulonglong2 B3 = *(const ulonglong2*)&shBd[k * 256 + 128 + (ty << 3) + 4];
            u64 ap[4] = {A0.x, A0.y, A1.x, A1.y};
            u64 bd[8] = {B0.x, B0.y, B1.x, B1.y, B2.x, B2.y, B3.x, B3.y};
#pragma unroll
            for (int i = 0; i < 8; i++)
#pragma unroll
                for (int j = 0; j < 4; j++) ffma2(acc[i][j], ap[j], bd[i]);
        }
    }

#pragma unroll
    for (int ih = 0; ih < 2; ih++)
#pragma unroll
        for (int ii = 0; ii < 4; ii++) {
            int i = ih * 4 + ii;
            int n = n0 + ih * 64 + (ty << 2) + ii;
            float bb = __ldg(bl + n);
            float* dst = g_xz + ((size_t)t * G4U_ + n) * B_;
#pragma unroll
            for (int mh = 0; mh < 2; mh++) {
                float2 p0 = unpack2(acc[i][mh * 2]);
                float2 p1 = unpack2(acc[i][mh * 2 + 1]);
                float4 v = make_float4(p0.x + bb, p0.y + bb, p1.x + bb, p1.y + bb);
                *(float4*)(dst + (tx << 2) + mh * 64) = v;
            }
        }
}

// ---------------------------------------------------------------------------
// Kernel 2: persistent LSTM recurrence. 128 CTAs; CTA j owns units [4j,4j+4).
// h[t-1] read coalesced from L2 ([t][u][b] layout); W_rec pairs via LDS.128
// broadcast; 4 FFMA2 per k per thread. c-state in registers. SMEM = 32KB.
// ---------------------------------------------------------------------------
__global__ void __launch_bounds__(256, 1) k2_rec(const float* __restrict__ Wrec) {
    __shared__ __align__(16) float shw[512 * 16];   // [k][uu*8 + g*2 + v]

    int tid = threadIdx.x;
    int j = blockIdx.x;

    // Stage W_rec slice once: word = k*16 + (v>>1)*8 + g*2 + (v&1)
#pragma unroll
    for (int it = 0; it < 8; ++it) {
        int idx = (it << 8) + tid;      // 0..2047
        int k = idx >> 2, g = idx & 3;
        float4 w4 = *(const float4*)(Wrec + (size_t)k * G4U_ + (g << 9) + (j << 2));
        float* base = &shw[k * 16 + g * 2];
        base[0] = w4.x;   // v=0
        base[1] = w4.y;   // v=1
        base[8] = w4.z;   // v=2
        base[9] = w4.w;   // v=3
    }
    __syncthreads();

    int r  = tid & 127;
    int uu = tid >> 7;
    int u0 = (j << 2) + (uu << 1);
    int woff = uu << 3;

    float c0 = 0.f, c1 = 0.f;

    for (int t = 0; t < T_; ++t) {
        u64 acc2[4];
        const float* pz = g_xz + ((size_t)t * G4U_ + u0) * B_ + r;
#pragma unroll
        for (int g = 0; g < 4; ++g)
            acc2[g] = pack2(pz[(size_t)g * (U_ * B_)], pz[(size_t)g * (U_ * B_) + B_]);

        if (t > 0) {
            grid_barrier();
            const float* hp = g_hseq + (size_t)(t - 1) * U_ * B_ + r;
#pragma unroll 4
            for (int k = 0; k < U_; ++k) {
                float hv = __ldg(hp + (size_t)k * B_);
                u64 hd = dup2(hv);
                ulonglong2 w01 = *(const ulonglong2*)&shw[k * 16 + woff];
                ulonglong2 w23 = *(const ulonglong2*)&shw[k * 16 + woff + 4];
                ffma2(acc2[0], hd, w01.x);
                ffma2(acc2[1], hd, w01.y);
                ffma2(acc2[2], hd, w23.x);
                ffma2(acc2[3], hd, w23.y);
            }
        }

        // Keras gate order: i, f, g, o
        float2 zi = unpack2(acc2[0]);
        float2 zf = unpack2(acc2[1]);
        float2 zg = unpack2(acc2[2]);
        float2 zo = unpack2(acc2[3]);
        float i0 = sigmoidf_(zi.x), i1 = sigmoidf_(zi.y);
        float f0 = sigmoidf_(zf.x), f1 = sigmoidf_(zf.y);
        float g0 = tanhf_fast(zg.x), g1 = tanhf_fast(zg.y);
        float o0 = sigmoidf_(zo.x), o1 = sigmoidf_(zo.y);
        c0 = f0 * c0 + i0 * g0;
        c1 = f1 * c1 + i1 * g1;
        float h0 = o0 * tanhf_fast(c0);
        float h1 = o1 * tanhf_fast(c1);

        float* ho = g_hseq + ((size_t)t * U_ + u0) * B_ + r;
        ho[0]  = h0;
        ho[B_] = h1;
    }
}

// ---------------------------------------------------------------------------
// Kernel 3: out = softmax(relu((h*mask) @ W_dense + b_dense))
// CTA = 16 rows x 1024 cols; thread = 16 rows x 4 cols; accumulators stay
// packed u64 through the softmax phases (register budget <= 128, 2 CTA/SM).
// h staged [u][row] stride 20 (float4-aligned); W splats; 32 FFMA2/u/thread.
// ---------------------------------------------------------------------------
__global__ void __launch_bounds__(256, 2) k3_out(const float* __restrict__ Wd,
                                                 const float* __restrict__ bd,
                                                 const float* __restrict__ mask,
                                                 float* __restrict__ out) {
    __shared__ __align__(16) float shh[512 * 20];   // [u][row], stride 20
    __shared__ float sred[16][9];

    int tid = threadIdx.x;
    int blk = blockIdx.x;
    int t  = blk >> 3;
    int b0 = (blk & 7) << 4;

    // fill from [t][u][b] layout: idx -> (u, 4-row group)
#pragma unroll
    for (int it = 0; it < 8; ++it) {
        int idx = (it << 8) + tid;          // 0..2047 float4 slots
        int u = idx >> 2, iq = (idx & 3) << 2;
        float4 h4 = *(const float4*)(g_hseq + ((size_t)t * U_ + u) * B_ + b0 + iq);
        float4 m4 = *(const float4*)(mask + t * B_ + b0 + iq);
        h4.x *= m4.x; h4.y *= m4.y; h4.z *= m4.z; h4.w *= m4.w;
        *(float4*)&shh[u * 20 + iq] = h4;
    }
    __syncthreads();

    int c4 = tid << 2;
    u64 acc2[8][4];
#pragma unroll
    for (int rp = 0; rp < 8; rp++)
#pragma unroll
        for (int jj = 0; jj < 4; jj++) acc2[rp][jj] = 0ull;

#pragma unroll 2
    for (int u = 0; u < U_; ++u) {
        float4 w4 = *(const float4*)(Wd + (size_t)u * CODES_ + c4);
        u64 wd0 = dup2(w4.x), wd1 = dup2(w4.y), wd2 = dup2(w4.z), wd3 = dup2(w4.w);
        const u64* hp = (const u64*)&shh[u * 20];
#pragma unroll
        for (int rp = 0; rp < 8; ++rp) {
            u64 h2 = hp[rp];
            ffma2(acc2[rp][0], h2, wd0);
            ffma2(acc2[rp][1], h2, wd1);
            ffma2(acc2[rp][2], h2, wd2);
            ffma2(acc2[rp][3], h2, wd3);
        }
    }

    float4 b4 = *(const float4*)(bd + c4);
    float bb[4] = {b4.x, b4.y, b4.z, b4.w};
    int wid = tid >> 5, lane = tid & 31;

    // Phase A: bias + relu (in place), rowwise max
    float rmax[16];
#pragma unroll
    for (int rp = 0; rp < 8; ++rp) {
        float m0 = -1e30f, m1 = -1e30f;
#pragma unroll
        for (int jj = 0; jj < 4; jj++) {
            float2 p = unpack2(acc2[rp][jj]);
            p.x = fmaxf(p.x + bb[jj], 0.f);
            p.y = fmaxf(p.y + bb[jj], 0.f);
            acc2[rp][jj] = pack2(p.x, p.y);
            m0 = fmaxf(m0, p.x);
            m1 = fmaxf(m1, p.y);
        }
#pragma unroll
        for (int s = 16; s > 0; s >>= 1) {
            m0 = fmaxf(m0, __shfl_xor_sync(0xFFFFFFFFu, m0, s));
            m1 = fmaxf(m1, __shfl_xor_sync(0xFFFFFFFFu, m1, s));
        }
        rmax[rp * 2]     = m0;
        rmax[rp * 2 + 1] = m1;
    }
    if (lane == 0) {
#pragma unroll
        for (int rr = 0; rr < 16; ++rr) sred[rr][wid] = rmax[rr];
    }
    __syncthreads();
    if (tid < 16) {
        float m = sred[tid][0];
#pragma unroll
        for (int w = 1; w < 8; w++) m = fmaxf(m, sred[tid][w]);
        sred[tid][8] = m;
    }
    __syncthreads();
#pragma unroll
    for (int rr = 0; rr < 16; ++rr) rmax[rr] = sred[rr][8];
    __syncthreads();   // everyone read the maxes before sred is reused

    // Phase B: exp (in place), rowwise sum
    float rsum[16];
#pragma unroll
    for (int rp = 0; rp < 8; ++rp) {
        float s0 = 0.f, s1 = 0.f;
        float mx0 = rmax[rp * 2], mx1 = rmax[rp * 2 + 1];
#pragma unroll
        for (int jj = 0; jj < 4; jj++) {
            float2 p = unpack2(acc2[rp][jj]);
            p.x = __expf(p.x - mx0);
            p.y = __expf(p.y - mx1);
            acc2[rp][jj] = pack2(p.x, p.y);
            s0 += p.x;
            s1 += p.y;
        }
#pragma unroll
        for (int st = 16; st > 0; st >>= 1) {
            s0 += __shfl_xor_sync(0xFFFFFFFFu, s0, st);
            s1 += __shfl_xor_sync(0xFFFFFFFFu, s1, st);
        }
        rsum[rp * 2]     = s0;
        rsum[rp * 2 + 1] = s1;
    }
    if (lane == 0) {
#pragma unroll
        for (int rr = 0; rr < 16; ++rr) sred[rr][wid] = rsum[rr];
    }
    __syncthreads();
    if (tid < 16) {
        float s = 0.f;
#pragma unroll
        for (int w = 0; w < 8; w++) s += sred[tid][w];
        sred[tid][8] = s;
    }
    __syncthreads();

#pragma unroll
    for (int rp = 0; rp < 8; ++rp) {
#pragma unroll
        for (int par = 0; par < 2; ++par) {
            int rr = rp * 2 + par;
            float inv = __frcp_rn(sred[rr][8]);
            float4 o;
            float2 p0 = unpack2(acc2[rp][0]);
            float2 p1 = unpack2(acc2[rp][1]);
            float2 p2 = unpack2(acc2[rp][2]);
            float2 p3 = unpack2(acc2[rp][3]);
            if (par == 0) { o.x = p0.x; o.y = p1.x; o.z = p2.x; o.w = p3.x; }
            else          { o.x = p0.y; o.y = p1.y; o.z = p2.y; o.w = p3.y; }
            o.x *= inv; o.y *= inv; o.z *= inv; o.w *= inv;
            *(float4*)(out + (size_t)(t * B_ + b0 + rr) * CODES_ + c4) = o;
        }
    }
}

// ---------------------------------------------------------------------------
extern "C" void kernel_launch(void* const* d_in, const int* in_sizes, int n_in,
                              void* d_out, int out_size) {
    const float* x    = (const float*)d_in[0];
    const float* mask = (const float*)d_in[1];
    const float* Win  = (const float*)d_in[2];
    const float* Wrec = (const float*)d_in[3];
    const float* bl   = (const float*)d_in[4];
    const float* Wd   = (const float*)d_in[5];
    const float* bd   = (const float*)d_in[6];
    float* out = (float*)d_out;

    dim3 g1(G4U_ / 128, T_);
    k1_xz<<<g1, 256>>>(x, Win, bl);
    k2_rec<<<NCTA2, 256>>>(Wrec);
    k3_out<<<(T_ * B_) / 16, 256>>>(Wd, bd, mask, out);
}